// round 8
// baseline (speedup 1.0000x reference)
#include <cuda_runtime.h>
#include <math.h>

#define NB 32
#define NS 4096
#define ND 512
#define NCHUNK 32
#define ROWS_PER_CHUNK (NS / NCHUNK)        // 128
#define T1 128
#define BIGV 10000.0f

// packed partials: (sum, max, min, acc) per (batch, chunk, col) = 8.4 MB
__device__ float4 g_part[NB][NCHUNK][ND];
__device__ float  g_pm [NB][NCHUNK];
__device__ float  g_pl [NB][NCHUNK];
__device__ float  g_pcnt[NB][NCHUNK];

__device__ __forceinline__ float dot4(const float4& a, const float4& b) {
    return a.x * b.x + a.y * b.y + a.z * b.z + a.w * b.w;
}

__global__ __launch_bounds__(T1) void pool_pass1(
    const float* __restrict__ x,
    const int* __restrict__ mask,   // 4-byte mask (int32 {0,1} or f32 {0.,1.}): nonzero-bits test exact
    const float* __restrict__ w)
{
    const int chunk = blockIdx.x;
    const int b     = blockIdx.y;
    const int t     = threadIdx.x;
    const int lane  = t & 31;
    const int wid   = t >> 5;

    __shared__ int   s_list[ROWS_PER_CHUNK];   // block-level compacted active rows
    __shared__ int   s_cnt4[4];
    __shared__ float s_m[4], s_l[4], s_cnt[4];
    __shared__ float s_mrg[2][4][ND];          // two planes, reused in two merge stages (16 KB)

    float4 w4[4];
    #pragma unroll
    for (int k = 0; k < 4; k++)
        w4[k] = *reinterpret_cast<const float4*>(w + k * 128 + lane * 4);

    float4 vsum[4], vmax[4], vmin[4], vacc[4];
    #pragma unroll
    for (int k = 0; k < 4; k++) {
        vsum[k] = make_float4(0.f, 0.f, 0.f, 0.f);
        vmax[k] = make_float4(-BIGV, -BIGV, -BIGV, -BIGV);
        vmin[k] = make_float4( BIGV,  BIGV,  BIGV,  BIGV);
        vacc[k] = make_float4(0.f, 0.f, 0.f, 0.f);
    }
    float m = -1e30f, l = 0.f, cnt = 0.f;

    const int rowbase = chunk * ROWS_PER_CHUNK;
    const float* xb = x + (size_t)b * NS * ND;

    // ---- block-level compaction of 128 rows (balanced 4-way split)
    const int  myrow = wid * 32 + lane;
    const bool a = (mask[(size_t)b * NS + rowbase + myrow] != 0);
    const unsigned bal = __ballot_sync(0xffffffffu, a);
    if (lane == 0) s_cnt4[wid] = __popc(bal);
    __syncthreads();
    int off = 0;
    #pragma unroll
    for (int wv = 0; wv < 4; wv++) if (wv < wid) off += s_cnt4[wv];
    const int ntot = s_cnt4[0] + s_cnt4[1] + s_cnt4[2] + s_cnt4[3];
    if (a) s_list[off + __popc(bal & ((1u << lane) - 1u))] = myrow;
    __syncthreads();

    const int per  = (ntot + 3) >> 2;
    const int ibeg = wid * per;
    const int iend = min(ibeg + per, ntot);

    // ---- dense main loop: 4 active rows per iteration, unconditional loads
    int i = ibeg;
    for (; i + 4 <= iend; i += 4) {
        float4 v[4][4];
        #pragma unroll
        for (int j = 0; j < 4; j++) {
            const float* p = xb + (size_t)(rowbase + s_list[i + j]) * ND + lane * 4;
            #pragma unroll
            for (int k = 0; k < 4; k++)
                v[j][k] = *reinterpret_cast<const float4*>(p + k * 128);
        }
        float d[4];
        #pragma unroll
        for (int j = 0; j < 4; j++)
            d[j] = dot4(v[j][0], w4[0]) + dot4(v[j][1], w4[1])
                 + dot4(v[j][2], w4[2]) + dot4(v[j][3], w4[3]);
        #pragma unroll
        for (int offs = 16; offs > 0; offs >>= 1) {
            #pragma unroll
            for (int j = 0; j < 4; j++)
                d[j] += __shfl_xor_sync(0xffffffffu, d[j], offs);
        }

        float newm = m;
        #pragma unroll
        for (int j = 0; j < 4; j++) newm = fmaxf(newm, d[j]);
        const float scale = __expf(m - newm);
        m = newm;
        l *= scale;
        float e[4];
        #pragma unroll
        for (int j = 0; j < 4; j++) { e[j] = __expf(d[j] - m); l += e[j]; }
        cnt += 4.f;

        #pragma unroll
        for (int k = 0; k < 4; k++) {
            float* A  = reinterpret_cast<float*>(&vacc[k]);
            float* S  = reinterpret_cast<float*>(&vsum[k]);
            float* Mx = reinterpret_cast<float*>(&vmax[k]);
            float* Mn = reinterpret_cast<float*>(&vmin[k]);
            #pragma unroll
            for (int c = 0; c < 4; c++) {
                const float x0 = reinterpret_cast<float*>(&v[0][k])[c];
                const float x1 = reinterpret_cast<float*>(&v[1][k])[c];
                const float x2 = reinterpret_cast<float*>(&v[2][k])[c];
                const float x3 = reinterpret_cast<float*>(&v[3][k])[c];
                A[c]  = A[c] * scale + e[0] * x0 + e[1] * x1 + e[2] * x2 + e[3] * x3;
                S[c] += (x0 + x1) + (x2 + x3);
                Mx[c] = fmaxf(Mx[c], fmaxf(fmaxf(x0, x1), fmaxf(x2, x3)));
                Mn[c] = fminf(Mn[c], fminf(fminf(x0, x1), fminf(x2, x3)));
            }
        }
    }
    for (; i < iend; i++) {   // tail
        const float* p = xb + (size_t)(rowbase + s_list[i]) * ND + lane * 4;
        float4 v0[4];
        #pragma unroll
        for (int k = 0; k < 4; k++) v0[k] = *reinterpret_cast<const float4*>(p + k * 128);
        float d0 = dot4(v0[0], w4[0]) + dot4(v0[1], w4[1])
                 + dot4(v0[2], w4[2]) + dot4(v0[3], w4[3]);
        #pragma unroll
        for (int offs = 16; offs > 0; offs >>= 1)
            d0 += __shfl_xor_sync(0xffffffffu, d0, offs);
        const float newm  = fmaxf(m, d0);
        const float scale = __expf(m - newm);
        m = newm;
        l *= scale;
        const float e0 = __expf(d0 - m);
        l += e0;
        cnt += 1.f;
        #pragma unroll
        for (int k = 0; k < 4; k++) {
            float* A  = reinterpret_cast<float*>(&vacc[k]);
            float* S  = reinterpret_cast<float*>(&vsum[k]);
            float* Mx = reinterpret_cast<float*>(&vmax[k]);
            float* Mn = reinterpret_cast<float*>(&vmin[k]);
            #pragma unroll
            for (int c = 0; c < 4; c++) {
                const float x0 = reinterpret_cast<float*>(&v0[k])[c];
                A[c]  = A[c] * scale + e0 * x0;
                S[c] += x0;
                Mx[c] = fmaxf(Mx[c], x0);
                Mn[c] = fminf(Mn[c], x0);
            }
        }
    }

    // ---- two-stage merge across 4 warps (smem plane reuse), packed float4 output
    if (lane == 0) { s_m[wid] = m; s_cnt[wid] = cnt; }
    #pragma unroll
    for (int k = 0; k < 4; k++) {
        const int c = k * 128 + lane * 4;
        *reinterpret_cast<float4*>(&s_mrg[0][wid][c]) = vsum[k];
        *reinterpret_cast<float4*>(&s_mrg[1][wid][c]) = vmax[k];
    }
    __syncthreads();

    const float M  = fmaxf(fmaxf(s_m[0], s_m[1]), fmaxf(s_m[2], s_m[3]));
    const float sc = __expf(m - M);

    const int c0 = t * 4;
    float4 osum = *reinterpret_cast<float4*>(&s_mrg[0][0][c0]);
    float4 omax = *reinterpret_cast<float4*>(&s_mrg[1][0][c0]);
    #pragma unroll
    for (int wi = 1; wi < 4; wi++) {
        const float4 q0 = *reinterpret_cast<float4*>(&s_mrg[0][wi][c0]);
        const float4 q1 = *reinterpret_cast<float4*>(&s_mrg[1][wi][c0]);
        osum.x += q0.x; osum.y += q0.y; osum.z += q0.z; osum.w += q0.w;
        omax.x = fmaxf(omax.x, q1.x); omax.y = fmaxf(omax.y, q1.y);
        omax.z = fmaxf(omax.z, q1.z); omax.w = fmaxf(omax.w, q1.w);
    }
    __syncthreads();   // protect plane reuse

    #pragma unroll
    for (int k = 0; k < 4; k++) {
        const int c = k * 128 + lane * 4;
        *reinterpret_cast<float4*>(&s_mrg[0][wid][c]) = vmin[k];
        float4 av = vacc[k];
        av.x *= sc; av.y *= sc; av.z *= sc; av.w *= sc;
        *reinterpret_cast<float4*>(&s_mrg[1][wid][c]) = av;
    }
    if (lane == 0) s_l[wid] = l * sc;
    __syncthreads();

    float4 omin = *reinterpret_cast<float4*>(&s_mrg[0][0][c0]);
    float4 oacc = *reinterpret_cast<float4*>(&s_mrg[1][0][c0]);
    #pragma unroll
    for (int wi = 1; wi < 4; wi++) {
        const float4 q0 = *reinterpret_cast<float4*>(&s_mrg[0][wi][c0]);
        const float4 q1 = *reinterpret_cast<float4*>(&s_mrg[1][wi][c0]);
        omin.x = fminf(omin.x, q0.x); omin.y = fminf(omin.y, q0.y);
        omin.z = fminf(omin.z, q0.z); omin.w = fminf(omin.w, q0.w);
        oacc.x += q1.x; oacc.y += q1.y; oacc.z += q1.z; oacc.w += q1.w;
    }

    // packed writes: one float4 per column
    const float* su = reinterpret_cast<const float*>(&osum);
    const float* mx = reinterpret_cast<const float*>(&omax);
    const float* mn = reinterpret_cast<const float*>(&omin);
    const float* ac = reinterpret_cast<const float*>(&oacc);
    #pragma unroll
    for (int j = 0; j < 4; j++)
        g_part[b][chunk][c0 + j] = make_float4(su[j], mx[j], mn[j], ac[j]);

    if (t == 0) {
        g_pm[b][chunk]   = M;
        g_pl[b][chunk]   = s_l[0] + s_l[1] + s_l[2] + s_l[3];
        g_pcnt[b][chunk] = s_cnt[0] + s_cnt[1] + s_cnt[2] + s_cnt[3];
    }
}

// pass2: grid (NB, 16) = 512 blocks × 512 threads; block = 32 cols;
// thread (half, col): combines chunks {half, half+16}; 16-way smem reduce.
#define T2 512
#define P2_COLS 32
#define P2_HALF 16

__global__ __launch_bounds__(T2) void pool_pass2(float* __restrict__ out)
{
    const int b    = blockIdx.x;
    const int tid  = threadIdx.x;
    const int lc   = tid & (P2_COLS - 1);
    const int half = tid >> 5;              // 0..15
    const int col  = blockIdx.y * P2_COLS + lc;

    __shared__ float  s_wc[NCHUNK];
    __shared__ float  s_invcnt;
    __shared__ float4 s_red[P2_HALF][P2_COLS];

    if (tid < 32) {   // per-batch softmax weights, one lane per chunk
        const float mc = g_pm[b][tid];
        const float lcn = g_pl[b][tid];
        const float cc = g_pcnt[b][tid];
        float M = mc;
        #pragma unroll
        for (int o = 16; o > 0; o >>= 1)
            M = fmaxf(M, __shfl_xor_sync(0xffffffffu, M, o));
        const float ec = __expf(mc - M);
        float L = lcn * ec, C = cc;
        #pragma unroll
        for (int o = 16; o > 0; o >>= 1) {
            L += __shfl_xor_sync(0xffffffffu, L, o);
            C += __shfl_xor_sync(0xffffffffu, C, o);
        }
        s_wc[tid] = ec / L;
        if (tid == 0) s_invcnt = 1.f / (C + 1e-6f);
    }
    __syncthreads();

    const float4 p0 = g_part[b][half][col];
    const float4 p1 = g_part[b][half + 16][col];
    s_red[half][lc] = make_float4(
        p0.x + p1.x,
        fmaxf(p0.y, p1.y),
        fminf(p0.z, p1.z),
        p0.w * s_wc[half] + p1.w * s_wc[half + 16]);
    __syncthreads();

    if (half == 0) {   // warp 0: one col per lane, reduce 16 slices
        float4 r = s_red[0][lc];
        #pragma unroll
        for (int s = 1; s < P2_HALF; s++) {
            const float4 q = s_red[s][lc];
            r.x += q.x;
            r.y = fmaxf(r.y, q.y);
            r.z = fminf(r.z, q.z);
            r.w += q.w;
        }
        float* ob = out + (size_t)b * (4 * ND);
        ob[col]          = r.x * s_invcnt;
        ob[ND + col]     = r.y;
        ob[2 * ND + col] = r.z;
        ob[3 * ND + col] = r.w;    // weights already normalized by 1/L
    }
}

extern "C" void kernel_launch(void* const* d_in, const int* in_sizes, int n_in,
                              void* d_out, int out_size)
{
    const float* x  = (const float*)d_in[0];
    const int*   mk = (const int*)d_in[1];
    const float* w  = (const float*)d_in[2];
    float* out      = (float*)d_out;

    dim3 grid1(NCHUNK, NB);          // (32, 32) = 1024 CTAs
    pool_pass1<<<grid1, T1>>>(x, mk, w);
    dim3 grid2(NB, ND / P2_COLS);    // (32, 16) = 512 CTAs
    pool_pass2<<<grid2, T2>>>(out);
}